// round 2
// baseline (speedup 1.0000x reference)
#include <cuda_runtime.h>
#include <cuda_bf16.h>
#include <cstdint>
#include <cstddef>

// ============================================================================
// Problem: out[8192,4096] = x[8192,4096] @ ternarize(W)[4096,4096]^T, fp32.
// Path: TF32 mma.sync (sm_100 baseline has no tcgen05 in this toolchain).
// Ternary weights are exact in tf32; x -> cvt.rna.tf32 (rel err ~2^-11).
// ============================================================================
#define M_DIM 8192
#define N_DIM 4096
#define K_DIM 4096

#define BM 128
#define BN 128
#define BK 32
#define STAGES 3
#define K_ITERS (K_DIM / BK)        // 128
#define THREADS 256

#define A_STAGE_BYTES (BM * BK * 4)          // 16384
#define B_STAGE_BYTES (BN * BK * 4)          // 16384
#define STAGE_BYTES   (A_STAGE_BYTES + B_STAGE_BYTES)   // 32768
#define SMEM_TOTAL    (STAGES * STAGE_BYTES)            // 98304

// Ternarized weight scratch (f32, exact in tf32). Static global: no allocs.
__device__ __align__(16) float g_Wt[(size_t)N_DIM * K_DIM];   // 64 MB

// ============================================================================
// Helpers
// ============================================================================
__device__ __forceinline__ uint32_t smem_u32(const void* p) {
    uint32_t a;
    asm("{ .reg .u64 t; cvta.to.shared.u64 t, %1; cvt.u32.u64 %0, t; }" : "=r"(a) : "l"(p));
    return a;
}
__device__ __forceinline__ void cp_async16(uint32_t dst, const void* src) {
    asm volatile("cp.async.cg.shared.global [%0], [%1], 16;" :: "r"(dst), "l"(src) : "memory");
}
__device__ __forceinline__ void cp_commit() { asm volatile("cp.async.commit_group;" ::: "memory"); }
__device__ __forceinline__ void cp_wait1()  { asm volatile("cp.async.wait_group 1;" ::: "memory"); }

__device__ __forceinline__ float lds_f32(uint32_t addr) {
    float v;
    asm volatile("ld.shared.f32 %0, [%1];" : "=f"(v) : "r"(addr));
    return v;
}
__device__ __forceinline__ uint32_t lds_u32(uint32_t addr) {
    uint32_t v;
    asm volatile("ld.shared.b32 %0, [%1];" : "=r"(v) : "r"(addr));
    return v;
}
__device__ __forceinline__ uint32_t f2tf32(float v) {
    uint32_t o;
    asm("cvt.rna.tf32.f32 %0, %1;" : "=r"(o) : "f"(v));
    return o;
}
__device__ __forceinline__ void mma_tf32(float& d0, float& d1, float& d2, float& d3,
                                         uint32_t a0, uint32_t a1, uint32_t a2, uint32_t a3,
                                         uint32_t b0, uint32_t b1) {
    asm volatile("mma.sync.aligned.m16n8k8.row.col.f32.tf32.tf32.f32 "
                 "{%0,%1,%2,%3}, {%4,%5,%6,%7}, {%8,%9}, {%0,%1,%2,%3};"
                 : "+f"(d0), "+f"(d1), "+f"(d2), "+f"(d3)
                 : "r"(a0), "r"(a1), "r"(a2), "r"(a3), "r"(b0), "r"(b1));
}

// Swizzled smem offset for tile element (row, col):  row-major, 32 f32/row,
// 16B chunks XOR-permuted by row to kill bank conflicts.
__device__ __forceinline__ uint32_t tile_off(int row, int col) {
    return (uint32_t)(row * 128 + ((((col >> 2) ^ (row & 7)) << 4) | ((col & 3) << 2)));
}

// ============================================================================
// W ternarize pre-pass: g_Wt = sign(rint(W)), matching jnp.sign(jnp.round(w))
// ============================================================================
__device__ __forceinline__ float tern(float w) {
    float r = rintf(w);                       // half-to-even
    return (r > 0.f) ? 1.f : ((r < 0.f) ? -1.f : 0.f);
}
__global__ void cvt_w_kernel(const float* __restrict__ w) {
    size_t q = (size_t)blockIdx.x * blockDim.x + threadIdx.x;   // 4194304 quads
    float4 v = reinterpret_cast<const float4*>(w)[q];
    float4 o = make_float4(tern(v.x), tern(v.y), tern(v.z), tern(v.w));
    *reinterpret_cast<float4*>(g_Wt + q * 4) = o;
}

// ============================================================================
// GEMM kernel
// ============================================================================
__global__ __launch_bounds__(THREADS, 2) void ternary_gemm_kernel(
    const float* __restrict__ x, float* __restrict__ out) {
    extern __shared__ char smem[];
    const uint32_t sb = smem_u32(smem);
    const int tid = threadIdx.x;

    // --- supergrouped rasterization: 8 M-tiles x all 32 N-tiles per group ---
    const int TILES_N = N_DIM / BN;           // 32
    const int GM = 8;
    const int per_super = GM * TILES_N;       // 256
    int gid = blockIdx.x;
    int sg = gid / per_super;
    int r  = gid % per_super;
    const int M0 = (sg * GM + (r % GM)) * BM;
    const int N0 = (r / GM) * BN;

    // --- loader address precompute: 4 A-chunks + 4 B-chunks per thread ------
    // chunk id space: 1024 chunks (128 rows x 8 x 16B) per matrix per stage
    int row4[4], ch4[4];
    const float* srcA[4];
    const float* srcB[4];
    uint32_t dstOff[4];
#pragma unroll
    for (int t = 0; t < 4; t++) {
        int cid = tid + t * 256;
        int row = cid >> 3;
        int ch  = cid & 7;
        row4[t] = row; ch4[t] = ch;
        srcA[t] = x    + (size_t)(M0 + row) * K_DIM + ch * 4;
        srcB[t] = g_Wt + (size_t)(N0 + row) * K_DIM + ch * 4;
        dstOff[t] = (uint32_t)(row * 128 + ((ch ^ (row & 7)) << 4));
    }

    auto issue_stage = [&](int i) {
        const int k0 = i * BK;
        const uint32_t aS = sb + (i % STAGES) * STAGE_BYTES;
        const uint32_t bS = aS + A_STAGE_BYTES;
#pragma unroll
        for (int t = 0; t < 4; t++) cp_async16(aS + dstOff[t], srcA[t] + k0);
#pragma unroll
        for (int t = 0; t < 4; t++) cp_async16(bS + dstOff[t], srcB[t] + k0);
        cp_commit();
    };

    // prologue: 2 stages in flight
    issue_stage(0);
    issue_stage(1);

    // --- warp tiling: 4 warps on M (32 rows each), 2 on N (64 cols each) ----
    const int wid = tid >> 5;
    const int lane = tid & 31;
    const int grp = lane >> 2;                // 0..7
    const int qid = lane & 3;                 // 0..3
    const int wmBase = (wid & 3) * 32;
    const int wnBase = (wid >> 2) * 64;

    float acc[2][8][4];
#pragma unroll
    for (int mt = 0; mt < 2; mt++)
#pragma unroll
        for (int nt = 0; nt < 8; nt++)
#pragma unroll
            for (int j = 0; j < 4; j++) acc[mt][nt][j] = 0.f;

#pragma unroll 1
    for (int i = 0; i < K_ITERS; i++) {
        cp_wait1();                // stage i landed
        __syncthreads();           // everyone done reading buf (i-1)%3 too
        if (i + 2 < K_ITERS) issue_stage(i + 2);
        else cp_commit();          // keep group accounting uniform

        const uint32_t aS = sb + (i % STAGES) * STAGE_BYTES;
        const uint32_t bS = aS + A_STAGE_BYTES;

#pragma unroll
        for (int ks = 0; ks < 4; ks++) {
            const int k = ks * 8;
            // A fragments (2 m-tiles x 4 regs), cvt.rna -> tf32
            uint32_t a[2][4];
#pragma unroll
            for (int mt = 0; mt < 2; mt++) {
                int r0 = wmBase + mt * 16 + grp;
                a[mt][0] = f2tf32(lds_f32(aS + tile_off(r0,     k + qid)));
                a[mt][1] = f2tf32(lds_f32(aS + tile_off(r0 + 8, k + qid)));
                a[mt][2] = f2tf32(lds_f32(aS + tile_off(r0,     k + qid + 4)));
                a[mt][3] = f2tf32(lds_f32(aS + tile_off(r0 + 8, k + qid + 4)));
            }
            // B fragments (8 n-tiles x 2 regs) — ternary values exact in tf32
            uint32_t b[8][2];
#pragma unroll
            for (int nt = 0; nt < 8; nt++) {
                int n = wnBase + nt * 8 + grp;
                b[nt][0] = lds_u32(bS + tile_off(n, k + qid));
                b[nt][1] = lds_u32(bS + tile_off(n, k + qid + 4));
            }
#pragma unroll
            for (int mt = 0; mt < 2; mt++)
#pragma unroll
                for (int nt = 0; nt < 8; nt++)
                    mma_tf32(acc[mt][nt][0], acc[mt][nt][1], acc[mt][nt][2], acc[mt][nt][3],
                             a[mt][0], a[mt][1], a[mt][2], a[mt][3],
                             b[nt][0], b[nt][1]);
        }
    }

    // --- epilogue: direct STG.64 (float2), coalesced per 8-col n-tile -------
#pragma unroll
    for (int mt = 0; mt < 2; mt++) {
        int row0 = M0 + wmBase + mt * 16 + grp;
#pragma unroll
        for (int nt = 0; nt < 8; nt++) {
            int col = N0 + wnBase + nt * 8 + qid * 2;
            float2 v0 = make_float2(acc[mt][nt][0], acc[mt][nt][1]);
            float2 v1 = make_float2(acc[mt][nt][2], acc[mt][nt][3]);
            *reinterpret_cast<float2*>(out + (size_t)row0 * N_DIM + col)       = v0;
            *reinterpret_cast<float2*>(out + (size_t)(row0 + 8) * N_DIM + col) = v1;
        }
    }
}

// ============================================================================
// Launch
// ============================================================================
extern "C" void kernel_launch(void* const* d_in, const int* in_sizes, int n_in,
                              void* d_out, int out_size) {
    const float* x = (const float*)d_in[0];       // [8192, 4096]
    const float* w = (const float*)d_in[1];       // [4096, 4096]
    float* out = (float*)d_out;                   // [8192, 4096]

    cvt_w_kernel<<<(N_DIM * (size_t)K_DIM / 4) / 256, 256>>>(w);

    static bool attr_set = false;
    if (!attr_set) {
        cudaFuncSetAttribute(ternary_gemm_kernel,
                             cudaFuncAttributeMaxDynamicSharedMemorySize, SMEM_TOTAL);
        attr_set = true;
    }
    const int grid = (M_DIM / BM) * (N_DIM / BN);     // 2048
    ternary_gemm_kernel<<<grid, THREADS, SMEM_TOTAL>>>(x, out);
}